// round 7
// baseline (speedup 1.0000x reference)
#include <cuda_runtime.h>

typedef unsigned long long u64;

#define B_  512
#define T_  512
#define F_  13
#define H_  128
#define O1_ 64
#define NT  384   // 8 rec warps + 4 fc warps

__device__ __forceinline__ u64 fma2(u64 a, u64 b, u64 c) {
    u64 d;
    asm("fma.rn.f32x2 %0, %1, %2, %3;" : "=l"(d) : "l"(a), "l"(b), "l"(c));
    return d;
}
__device__ __forceinline__ float f2sum(u64 a) {
    float lo, hi;
    asm("mov.b64 {%0, %1}, %2;" : "=f"(lo), "=f"(hi) : "l"(a));
    return lo + hi;
}
__device__ __forceinline__ u64 pack2(float lo, float hi) {
    u64 r;
    asm("mov.b64 %0, {%1, %2};" : "=l"(r) : "f"(lo), "f"(hi));
    return r;
}
// tanh(x) = 1 - 2/(1+e^{2x}); abs err ~1e-7, inf-safe.
__device__ __forceinline__ float tanh_fast(float x) {
    float e = __expf(2.f * x);
    return 1.f - __fdividef(2.f, 1.f + e);
}
__device__ __forceinline__ float sigmoid_fast(float s) {
    return __fdividef(1.f, 1.f + __expf(-s));
}

// ---------------------------------------------------------------------------
// Fused persistent RNN, 128 CTAs x 384 threads, 4 batch rows per CTA.
// Warp-specialized (disjoint weight sets -> register overlay, no spill),
// with PAIRED k-split on both sides: the low lane bit carries the k-half, so
// partial-dot exchange is a shfl_xor(1) inside the warp -> no smem relay, no
// second barrier. Hs/Xs/red are double-buffered -> ONE __syncthreads per step.
//
// Rec (tid 0..255): thread (j = tid>>1, kh = tid&1) holds W_hh[j][64kh:+64)
//   (32 u64 regs). Per step: inproj for rows {2kh,2kh+1} + partial recurrent
//   dots for all 4 rows over its k-half; shfl_xor(1) merges halves; tanh;
//   store its 2 rows of h(t) into Hs[cur^1]. 144 fma2/thread.
// FC (tid 256..383): thread (o = ft>>1, fkh = ft&1) holds fc1_w[o][64fkh:+64)
//   (32 u64 regs). At iter t>=1 reads Hs[cur] = h(t-1): partial dots for 4
//   rows; pair shfl merges halves; relu*fc2_w; warp bfly; lane0 -> red4.
//   4 threads emit sigmoid(0.5*sum + b2) one iteration later. 128 fma2/thread.
// ---------------------------------------------------------------------------
__global__ void __launch_bounds__(NT, 1) rnn_fused(
    const float* __restrict__ x,
    const float* __restrict__ W_ih,
    const float* __restrict__ W_hh,
    const float* __restrict__ b_ih,
    const float* __restrict__ b_hh,
    const float* __restrict__ fc1_w,
    const float* __restrict__ fc1_b,
    const float* __restrict__ fc2_w,
    const float* __restrict__ fc2_b,
    float* __restrict__ out)
{
    __shared__ __align__(16) float Hs[2][4 * H_];   // double-buffered h
    __shared__ __align__(16) float Xs[2][4 * 16];   // double-buffered x
    __shared__ float red4[2][4][4];                 // [buf][fc warp][row]

    const int tid  = threadIdx.x;
    const int row0 = blockIdx.x * 4;

    // ---- init: zero state, stage x_0 ----
    for (int i = tid; i < 2 * 4 * H_; i += NT) ((float*)Hs)[i] = 0.f;
    if (tid < 128) ((float*)Xs)[tid] = 0.f;
    __syncthreads();
    {
        int ft = tid - 256;
        if (ft >= 0 && ft < 52) {
            int pr = ft / 13, pf = ft - pr * 13;
            Xs[0][pr * 16 + pf] = x[((size_t)(row0 + pr) * T_) * F_ + pf];
        }
    }
    __syncthreads();

    int cur = 0;

    if (tid < 256) {
        // =================== RECURRENCE ===================
        const int j    = tid >> 1;       // 0..127
        const int kh   = tid & 1;        // k-half
        const int koff = kh * 64;
        const int own0 = 2 * kh;         // rows finalized by this thread
        const int oth0 = 2 - 2 * kh;

        u64 w[32];
        {
            const ulonglong2* wrow =
                (const ulonglong2*)(W_hh + (size_t)j * H_ + koff);
#pragma unroll
            for (int m = 0; m < 16; m++) {
                ulonglong2 v = wrow[m];
                w[2 * m] = v.x; w[2 * m + 1] = v.y;
            }
        }
        u64 wihp[8];
        {
            float wih[16];
#pragma unroll
            for (int f = 0; f < 16; f++)
                wih[f] = (f < F_) ? __ldg(W_ih + j * F_ + f) : 0.f;
#pragma unroll
            for (int q = 0; q < 8; q++)
                wihp[q] = pack2(wih[2 * q], wih[2 * q + 1]);
        }
        const float bsum = __ldg(b_ih + j) + __ldg(b_hh + j);

        for (int t = 0; t <= T_; t++) {
            if (t < T_) {
                const float* Hrd = Hs[cur];
                float* Hwr = Hs[cur ^ 1];

                u64 a0[4], a1[4];
#pragma unroll
                for (int r = 0; r < 4; r++) { a0[r] = 0ull; a1[r] = 0ull; }

                // input projection for own rows (full 16 padded features)
#pragma unroll
                for (int ri = 0; ri < 2; ri++) {
                    const int r = own0 + ri;
                    const ulonglong2* xr =
                        (const ulonglong2*)(Xs[cur] + r * 16);
                    ulonglong2 xa = xr[0], xb = xr[1], xc = xr[2], xd = xr[3];
                    a0[r] = fma2(xa.x, wihp[0], a0[r]);
                    a1[r] = fma2(xa.y, wihp[1], a1[r]);
                    a0[r] = fma2(xb.x, wihp[2], a0[r]);
                    a1[r] = fma2(xb.y, wihp[3], a1[r]);
                    a0[r] = fma2(xc.x, wihp[4], a0[r]);
                    a1[r] = fma2(xc.y, wihp[5], a1[r]);
                    a0[r] = fma2(xd.x, wihp[6], a0[r]);
                    a1[r] = fma2(xd.y, wihp[7], a1[r]);
                }
                // recurrent partials over this k-half, all 4 rows
#pragma unroll
                for (int m = 0; m < 16; m++) {
                    ulonglong2 h0 = *(const ulonglong2*)(Hrd + 0 * H_ + koff + 4 * m);
                    ulonglong2 h1 = *(const ulonglong2*)(Hrd + 1 * H_ + koff + 4 * m);
                    ulonglong2 h2 = *(const ulonglong2*)(Hrd + 2 * H_ + koff + 4 * m);
                    ulonglong2 h3 = *(const ulonglong2*)(Hrd + 3 * H_ + koff + 4 * m);
                    a0[0] = fma2(h0.x, w[2 * m], a0[0]);
                    a0[1] = fma2(h1.x, w[2 * m], a0[1]);
                    a0[2] = fma2(h2.x, w[2 * m], a0[2]);
                    a0[3] = fma2(h3.x, w[2 * m], a0[3]);
                    a1[0] = fma2(h0.y, w[2 * m + 1], a1[0]);
                    a1[1] = fma2(h1.y, w[2 * m + 1], a1[1]);
                    a1[2] = fma2(h2.y, w[2 * m + 1], a1[2]);
                    a1[3] = fma2(h3.y, w[2 * m + 1], a1[3]);
                }

                float own_s0 = bsum + f2sum(a0[own0])     + f2sum(a1[own0]);
                float own_s1 = bsum + f2sum(a0[own0 + 1]) + f2sum(a1[own0 + 1]);
                float c0 = f2sum(a0[oth0])     + f2sum(a1[oth0]);
                float c1 = f2sum(a0[oth0 + 1]) + f2sum(a1[oth0 + 1]);
                // partner (lane^1) holds the other k-half of MY rows
                float r0 = __shfl_xor_sync(0xffffffffu, c0, 1);
                float r1 = __shfl_xor_sync(0xffffffffu, c1, 1);

                Hwr[own0 * H_ + j]       = tanh_fast(own_s0 + r0);
                Hwr[(own0 + 1) * H_ + j] = tanh_fast(own_s1 + r1);
            }
            __syncthreads();
            cur ^= 1;
        }
    } else {
        // =================== FC HEAD ===================
        const int ft    = tid - 256;     // 0..127
        const int o     = ft >> 1;       // 0..63
        const int fkh   = ft & 1;
        const int fkoff = fkh * 64;
        const int wloc  = ft >> 5;       // 0..3
        const int lane  = ft & 31;

        u64 fw[32];
        {
            const ulonglong2* fr =
                (const ulonglong2*)(fc1_w + (size_t)o * H_ + fkoff);
#pragma unroll
            for (int m = 0; m < 16; m++) {
                ulonglong2 v = fr[m];
                fw[2 * m] = v.x; fw[2 * m + 1] = v.y;
            }
        }
        const float b1 = __ldg(fc1_b + o);
        const float w2 = __ldg(fc2_w + o);
        const float b2 = __ldg(fc2_b);

        const bool is_loader = (ft < 52);
        const int  pr = ft / 13, pf = ft - pr * 13;
        const float* xptr = x + ((size_t)(row0 + pr) * T_) * F_ + pf;

        for (int t = 0; t <= T_; t++) {
            // emit out index t-2 (combined last iteration, sep. by barrier)
            if (t >= 2 && ft < 4) {
                const int r = ft, bp = (t - 1) & 1;
                float s = red4[bp][0][r] + red4[bp][1][r]
                        + red4[bp][2][r] + red4[bp][3][r];
                out[(size_t)(row0 + r) * T_ + (t - 2)] =
                    sigmoid_fast(0.5f * s + b2);
            }

            // prefetch + stage x(t+1) into the other Xs buffer
            if (is_loader && t + 1 < T_)
                Xs[cur ^ 1][pr * 16 + pf] =
                    __ldg(xptr + (size_t)(t + 1) * F_);

            if (t >= 1) {
                const float* Hrd = Hs[cur];   // h(t-1), stable this interval
                u64 f0[4], f1[4];
#pragma unroll
                for (int r = 0; r < 4; r++) { f0[r] = 0ull; f1[r] = 0ull; }
#pragma unroll
                for (int m = 0; m < 16; m++) {
#pragma unroll
                    for (int r = 0; r < 4; r++) {
                        ulonglong2 hv =
                            *(const ulonglong2*)(Hrd + r * H_ + fkoff + 4 * m);
                        f0[r] = fma2(hv.x, fw[2 * m],     f0[r]);
                        f1[r] = fma2(hv.y, fw[2 * m + 1], f1[r]);
                    }
                }
                float y[4];
#pragma unroll
                for (int r = 0; r < 4; r++) {
                    float p = f2sum(f0[r]) + f2sum(f1[r]);
                    p += __shfl_xor_sync(0xffffffffu, p, 1);  // merge k-halves
                    y[r] = fmaxf(p + b1, 0.f) * w2;
                }
                // warp bfly: sum over lanes (each o counted twice -> 0.5 at emit)
#pragma unroll
                for (int off = 16; off > 0; off >>= 1) {
#pragma unroll
                    for (int r = 0; r < 4; r++)
                        y[r] += __shfl_xor_sync(0xffffffffu, y[r], off);
                }
                if (lane == 0) {
                    const int bn = t & 1;
#pragma unroll
                    for (int r = 0; r < 4; r++) red4[bn][wloc][r] = y[r];
                }
            }
            __syncthreads();
            cur ^= 1;
        }

        // final output index T-1 (combined at iter T, sep. by last barrier)
        if (ft < 4) {
            const int r = ft, bp = T_ & 1;
            float s = red4[bp][0][r] + red4[bp][1][r]
                    + red4[bp][2][r] + red4[bp][3][r];
            out[(size_t)(row0 + r) * T_ + (T_ - 1)] =
                sigmoid_fast(0.5f * s + b2);
        }
    }
}

// ---------------------------------------------------------------------------

extern "C" void kernel_launch(void* const* d_in, const int* in_sizes, int n_in,
                              void* d_out, int out_size)
{
    const float* x     = (const float*)d_in[0];
    const float* W_ih  = (const float*)d_in[1];
    const float* W_hh  = (const float*)d_in[2];
    const float* b_ih  = (const float*)d_in[3];
    const float* b_hh  = (const float*)d_in[4];
    const float* fc1_w = (const float*)d_in[5];
    const float* fc1_b = (const float*)d_in[6];
    const float* fc2_w = (const float*)d_in[7];
    const float* fc2_b = (const float*)d_in[8];
    float* out = (float*)d_out;

    rnn_fused<<<128, NT>>>(x, W_ih, W_hh, b_ih, b_hh,
                           fc1_w, fc1_b, fc2_w, fc2_b, out);
}

// round 8
// speedup vs baseline: 1.8415x; 1.8415x over previous
#include <cuda_runtime.h>

typedef unsigned long long u64;

#define B_  512
#define T_  512
#define F_  13
#define H_  128
#define NT  256

__device__ __forceinline__ u64 fma2(u64 a, u64 b, u64 c) {
    u64 d;
    asm("fma.rn.f32x2 %0, %1, %2, %3;" : "=l"(d) : "l"(a), "l"(b), "l"(c));
    return d;
}
__device__ __forceinline__ float f2sum(u64 a) {
    float lo, hi;
    asm("mov.b64 {%0, %1}, %2;" : "=f"(lo), "=f"(hi) : "l"(a));
    return lo + hi;
}
__device__ __forceinline__ u64 pack2(float lo, float hi) {
    u64 r;
    asm("mov.b64 %0, {%1, %2};" : "=l"(r) : "f"(lo), "f"(hi));
    return r;
}
// tanh(x) = 1 - 2/(1+e^{2x}); abs err ~1e-7, inf-safe.
__device__ __forceinline__ float tanh_fast(float x) {
    float e = __expf(2.f * x);
    return 1.f - __fdividef(2.f, 1.f + e);
}
__device__ __forceinline__ float sigmoid_fast(float s) {
    return __fdividef(1.f, 1.f + __expf(-s));
}

// ---------------------------------------------------------------------------
// Fused persistent RNN, 128 CTAs x 256 threads, 4 batch rows per CTA.
// Warp-specialized, j-paired + k-split on BOTH sides, single barrier per step.
//
// Rec (tid 0..127): thread (jj = tid>>1, kh = tid&1) holds W_hh rows
//   {jj, jj+64} over k-half [64kh, 64kh+64) -> 32 u64 weight regs. Each loaded
//   16B of h feeds 2 j-rows (LDS:fma2 = 1:4). Inproj for its 2 owned batch
//   rows {2kh, 2kh+1}. Cross-half partials merge via shfl_xor(1) (adjacent
//   lanes). tanh + STS into Hs[cur^1] pre-barrier.
// FC (tid 128..255): thread (kh2 = ft&1, oo = (ft>>1)&31, rp = ft>>6) holds
//   fc1_w rows {oo, oo+32} over k-half -> 32 u64 regs; 2 batch rows
//   {2rp, 2rp+1} on h(t) = Hs[cur]. k-merge shfl_xor(1), relu*fc2_w, sum the
//   o-pair, bfly over offsets 2,4,8,16; lane0 -> red[cur^1][rp][oohigh].
//   4 threads emit sigmoid one iteration later.
// Hs/Xs/red double-buffered: exactly ONE __syncthreads per iteration.
// ---------------------------------------------------------------------------
__global__ void __launch_bounds__(NT, 1) rnn_fused(
    const float* __restrict__ x,
    const float* __restrict__ W_ih,
    const float* __restrict__ W_hh,
    const float* __restrict__ b_ih,
    const float* __restrict__ b_hh,
    const float* __restrict__ fc1_w,
    const float* __restrict__ fc1_b,
    const float* __restrict__ fc2_w,
    const float* __restrict__ fc2_b,
    float* __restrict__ out)
{
    __shared__ __align__(16) float Hs[2][4 * H_];   // double-buffered h
    __shared__ __align__(16) float Xs[2][64];       // double-buffered x (4x16)
    __shared__ float2 red[2][2][2];                 // [buf][rp][oohigh]

    const int tid  = threadIdx.x;
    const int row0 = blockIdx.x * 4;

    // ---- init: zero state + padded x, stage x(0) ----
    for (int i = tid; i < 2 * 4 * H_; i += NT) ((float*)Hs)[i] = 0.f;
    if (tid < 128) ((float*)Xs)[tid] = 0.f;
    __syncthreads();
    if (tid < 52) {
        int pr = tid / 13, pf = tid - pr * 13;
        Xs[0][pr * 16 + pf] = x[((size_t)(row0 + pr) * T_) * F_ + pf];
    }
    __syncthreads();

    int cur = 0;

    if (tid < 128) {
        // =================== RECURRENCE ===================
        const int jj   = tid >> 1;       // 0..63 -> j rows {jj, jj+64}
        const int kh   = tid & 1;        // k-half
        const int koff = kh * 64;
        const int r0   = 2 * kh,     r1 = 2 * kh + 1;   // owned batch rows
        const int o0   = 2 - 2 * kh, o1 = 3 - 2 * kh;   // partner's rows

        u64 wA[32], wB[32];
        {
            const ulonglong2* ra =
                (const ulonglong2*)(W_hh + (size_t)jj * H_ + koff);
            const ulonglong2* rb =
                (const ulonglong2*)(W_hh + (size_t)(jj + 64) * H_ + koff);
#pragma unroll
            for (int m = 0; m < 16; m++) {
                ulonglong2 va = ra[m], vb = rb[m];
                wA[2 * m] = va.x; wA[2 * m + 1] = va.y;
                wB[2 * m] = vb.x; wB[2 * m + 1] = vb.y;
            }
        }
        u64 wihA[8], wihB[8];
        {
            float wa[16], wb[16];
#pragma unroll
            for (int f = 0; f < 16; f++) {
                wa[f] = (f < F_) ? __ldg(W_ih + jj * F_ + f) : 0.f;
                wb[f] = (f < F_) ? __ldg(W_ih + (jj + 64) * F_ + f) : 0.f;
            }
#pragma unroll
            for (int q = 0; q < 8; q++) {
                wihA[q] = pack2(wa[2 * q], wa[2 * q + 1]);
                wihB[q] = pack2(wb[2 * q], wb[2 * q + 1]);
            }
        }
        const float bsA = __ldg(b_ih + jj) + __ldg(b_hh + jj);
        const float bsB = __ldg(b_ih + jj + 64) + __ldg(b_hh + jj + 64);

        for (int t = 0; t <= T_; t++) {
            if (t < T_) {
                const float* Hrd = Hs[cur];
                float*       Hwr = Hs[cur ^ 1];
                const float* Xr  = Xs[cur];

                u64 aA[4], aB[4];
#pragma unroll
                for (int r = 0; r < 4; r++) { aA[r] = 0ull; aB[r] = 0ull; }

                // input projection for owned rows (j = jj and jj+64)
#pragma unroll
                for (int ri = 0; ri < 2; ri++) {
                    const int r = 2 * kh + ri;
                    const ulonglong2* xr = (const ulonglong2*)(Xr + r * 16);
                    ulonglong2 x0 = xr[0], x1 = xr[1], x2 = xr[2], x3 = xr[3];
                    aA[r] = fma2(x0.x, wihA[0], aA[r]);
                    aA[r] = fma2(x0.y, wihA[1], aA[r]);
                    aA[r] = fma2(x1.x, wihA[2], aA[r]);
                    aA[r] = fma2(x1.y, wihA[3], aA[r]);
                    aA[r] = fma2(x2.x, wihA[4], aA[r]);
                    aA[r] = fma2(x2.y, wihA[5], aA[r]);
                    aA[r] = fma2(x3.x, wihA[6], aA[r]);
                    aA[r] = fma2(x3.y, wihA[7], aA[r]);
                    aB[r] = fma2(x0.x, wihB[0], aB[r]);
                    aB[r] = fma2(x0.y, wihB[1], aB[r]);
                    aB[r] = fma2(x1.x, wihB[2], aB[r]);
                    aB[r] = fma2(x1.y, wihB[3], aB[r]);
                    aB[r] = fma2(x2.x, wihB[4], aB[r]);
                    aB[r] = fma2(x2.y, wihB[5], aB[r]);
                    aB[r] = fma2(x3.x, wihB[6], aB[r]);
                    aB[r] = fma2(x3.y, wihB[7], aB[r]);
                }

                // recurrent partials over this k-half; each 16B load feeds 2 j
#pragma unroll
                for (int m = 0; m < 16; m++) {
                    ulonglong2 h0 = *(const ulonglong2*)(Hrd + 0 * H_ + koff + 4 * m);
                    ulonglong2 h1 = *(const ulonglong2*)(Hrd + 1 * H_ + koff + 4 * m);
                    ulonglong2 h2 = *(const ulonglong2*)(Hrd + 2 * H_ + koff + 4 * m);
                    ulonglong2 h3 = *(const ulonglong2*)(Hrd + 3 * H_ + koff + 4 * m);
                    aA[0] = fma2(h0.x, wA[2 * m], aA[0]);
                    aA[1] = fma2(h1.x, wA[2 * m], aA[1]);
                    aA[2] = fma2(h2.x, wA[2 * m], aA[2]);
                    aA[3] = fma2(h3.x, wA[2 * m], aA[3]);
                    aB[0] = fma2(h0.x, wB[2 * m], aB[0]);
                    aB[1] = fma2(h1.x, wB[2 * m], aB[1]);
                    aB[2] = fma2(h2.x, wB[2 * m], aB[2]);
                    aB[3] = fma2(h3.x, wB[2 * m], aB[3]);
                    aA[0] = fma2(h0.y, wA[2 * m + 1], aA[0]);
                    aA[1] = fma2(h1.y, wA[2 * m + 1], aA[1]);
                    aA[2] = fma2(h2.y, wA[2 * m + 1], aA[2]);
                    aA[3] = fma2(h3.y, wA[2 * m + 1], aA[3]);
                    aB[0] = fma2(h0.y, wB[2 * m + 1], aB[0]);
                    aB[1] = fma2(h1.y, wB[2 * m + 1], aB[1]);
                    aB[2] = fma2(h2.y, wB[2 * m + 1], aB[2]);
                    aB[3] = fma2(h3.y, wB[2 * m + 1], aB[3]);
                }

                float pA0 = f2sum(aA[r0]), pA1 = f2sum(aA[r1]);
                float pB0 = f2sum(aB[r0]), pB1 = f2sum(aB[r1]);
                float qA0 = f2sum(aA[o0]), qA1 = f2sum(aA[o1]);
                float qB0 = f2sum(aB[o0]), qB1 = f2sum(aB[o1]);
                // partner (lane^1) holds the other k-half of MY rows; its
                // qA0 is its partial for row (its o0) = my r0. Symmetric swap.
                float eA0 = __shfl_xor_sync(0xffffffffu, qA0, 1);
                float eA1 = __shfl_xor_sync(0xffffffffu, qA1, 1);
                float eB0 = __shfl_xor_sync(0xffffffffu, qB0, 1);
                float eB1 = __shfl_xor_sync(0xffffffffu, qB1, 1);

                Hwr[r0 * H_ + jj]      = tanh_fast(pA0 + eA0 + bsA);
                Hwr[r1 * H_ + jj]      = tanh_fast(pA1 + eA1 + bsA);
                Hwr[r0 * H_ + jj + 64] = tanh_fast(pB0 + eB0 + bsB);
                Hwr[r1 * H_ + jj + 64] = tanh_fast(pB1 + eB1 + bsB);
            }
            __syncthreads();
            cur ^= 1;
        }
    } else {
        // =================== FC HEAD ===================
        const int ft    = tid - 128;       // 0..127
        const int kh2   = ft & 1;
        const int oo    = (ft >> 1) & 31;  // o rows {oo, oo+32}
        const int rp    = ft >> 6;         // batch rows {2rp, 2rp+1}
        const int lane  = ft & 31;
        const int ooh   = (ft >> 5) & 1;   // oo high bit
        const int koff2 = kh2 * 64;

        u64 fwA[32], fwB[32];
        {
            const ulonglong2* ra =
                (const ulonglong2*)(fc1_w + (size_t)oo * H_ + koff2);
            const ulonglong2* rb =
                (const ulonglong2*)(fc1_w + (size_t)(oo + 32) * H_ + koff2);
#pragma unroll
            for (int m = 0; m < 16; m++) {
                ulonglong2 va = ra[m], vb = rb[m];
                fwA[2 * m] = va.x; fwA[2 * m + 1] = va.y;
                fwB[2 * m] = vb.x; fwB[2 * m + 1] = vb.y;
            }
        }
        const float b1A = __ldg(fc1_b + oo);
        const float b1B = __ldg(fc1_b + oo + 32);
        const float w2A = __ldg(fc2_w + oo);
        const float w2B = __ldg(fc2_w + oo + 32);
        const float b2  = __ldg(fc2_b);

        const bool is_loader = (ft < 52);
        const int  pr = ft / 13, pf = ft - pr * 13;
        const float* xptr = x + ((size_t)(row0 + pr) * T_) * F_ + pf;

        for (int t = 0; t <= T_; t++) {
            // emit out index t-2 (combined at iter t-1, one barrier crossing)
            if (t >= 2 && ft < 4) {
                const int r = ft;
                float2 v0 = red[cur][r >> 1][0];
                float2 v1 = red[cur][r >> 1][1];
                float s = (r & 1) ? (v0.y + v1.y) : (v0.x + v1.x);
                out[(size_t)(row0 + r) * T_ + (t - 2)] = sigmoid_fast(s + b2);
            }

            // stage x(t+1) into the other Xs buffer
            if (is_loader && t + 1 < T_)
                Xs[cur ^ 1][pr * 16 + pf] = __ldg(xptr + (size_t)(t + 1) * F_);

            if (t >= 1) {
                const float* Hrd = Hs[cur];      // h(t), stable this interval
                const float* h0p = Hrd + (2 * rp) * H_ + koff2;
                const float* h1p = Hrd + (2 * rp + 1) * H_ + koff2;

                u64 q00 = 0ull, q01 = 0ull, q10 = 0ull, q11 = 0ull;
#pragma unroll
                for (int m = 0; m < 16; m++) {
                    ulonglong2 hv0 = *(const ulonglong2*)(h0p + 4 * m);
                    ulonglong2 hv1 = *(const ulonglong2*)(h1p + 4 * m);
                    q00 = fma2(hv0.x, fwA[2 * m], q00);
                    q01 = fma2(hv0.x, fwB[2 * m], q01);
                    q10 = fma2(hv1.x, fwA[2 * m], q10);
                    q11 = fma2(hv1.x, fwB[2 * m], q11);
                    q00 = fma2(hv0.y, fwA[2 * m + 1], q00);
                    q01 = fma2(hv0.y, fwB[2 * m + 1], q01);
                    q10 = fma2(hv1.y, fwA[2 * m + 1], q10);
                    q11 = fma2(hv1.y, fwB[2 * m + 1], q11);
                }
                float d00 = f2sum(q00), d01 = f2sum(q01);
                float d10 = f2sum(q10), d11 = f2sum(q11);
                // merge k-halves (partner = lane^1, same oo/rp)
                d00 += __shfl_xor_sync(0xffffffffu, d00, 1);
                d01 += __shfl_xor_sync(0xffffffffu, d01, 1);
                d10 += __shfl_xor_sync(0xffffffffu, d10, 1);
                d11 += __shfl_xor_sync(0xffffffffu, d11, 1);

                float z0 = fmaxf(d00 + b1A, 0.f) * w2A
                         + fmaxf(d01 + b1B, 0.f) * w2B;
                float z1 = fmaxf(d10 + b1A, 0.f) * w2A
                         + fmaxf(d11 + b1B, 0.f) * w2B;
                // reduce over oo low bits (offsets 2,4,8,16); even/odd lane
                // parities hold identical copies -> two identical reductions
#pragma unroll
                for (int off = 2; off <= 16; off <<= 1) {
                    z0 += __shfl_xor_sync(0xffffffffu, z0, off);
                    z1 += __shfl_xor_sync(0xffffffffu, z1, off);
                }
                if (lane == 0)
                    red[cur ^ 1][rp][ooh] = make_float2(z0, z1);
            }
            __syncthreads();
            cur ^= 1;
        }

        // final output index T-1 (combined at iter T, after last barrier)
        if (ft < 4) {
            const int r = ft;
            float2 v0 = red[cur][r >> 1][0];
            float2 v1 = red[cur][r >> 1][1];
            float s = (r & 1) ? (v0.y + v1.y) : (v0.x + v1.x);
            out[(size_t)(row0 + r) * T_ + (T_ - 1)] = sigmoid_fast(s + b2);
        }
    }
}

// ---------------------------------------------------------------------------

extern "C" void kernel_launch(void* const* d_in, const int* in_sizes, int n_in,
                              void* d_out, int out_size)
{
    const float* x     = (const float*)d_in[0];
    const float* W_ih  = (const float*)d_in[1];
    const float* W_hh  = (const float*)d_in[2];
    const float* b_ih  = (const float*)d_in[3];
    const float* b_hh  = (const float*)d_in[4];
    const float* fc1_w = (const float*)d_in[5];
    const float* fc1_b = (const float*)d_in[6];
    const float* fc2_w = (const float*)d_in[7];
    const float* fc2_b = (const float*)d_in[8];
    float* out = (float*)d_out;

    rnn_fused<<<128, NT>>>(x, W_ih, W_hh, b_ih, b_hh,
                           fc1_w, fc1_b, fc2_w, fc2_b, out);
}